// round 2
// baseline (speedup 1.0000x reference)
#include <cuda_runtime.h>

// Problem constants
#define B_   8
#define T_   1024
#define E_   256
#define H_   8
#define HE_  2048   // H_*E_

// GEMM tile config: 128x128 tile, BK=16, 256 threads, 8x8 microtile
#define BM   128
#define BN   128
#define BK   16
#define BMP  130    // padded smem row stride (2-float aligned, conflict-free-ish)

#define NEG_INF __int_as_float(0xff800000)

// Scratch (static device arrays: allocation-guard-safe)
// g_qkv holds Q, K, V each [B, T, HE]
__device__ float g_qkv[3ULL * B_ * T_ * HE_];
// g_s holds scores/probs [B*H, T, T]
__device__ float g_s[(size_t)B_ * H_ * T_ * T_];
// g_o holds attn@V result [B, T, HE]
__device__ float g_o[(size_t)B_ * T_ * HE_];

// ---------------------------------------------------------------------------
// GEMM mainloop: computes a BMxBN tile of A(MxK) * op(B)(KxN).
// BT=false: B is [K, N] row-major (ldb = row stride)
// BT=true : B is [N, K] row-major (ldb = row stride)  -> C = A * B^T
// A points at the tile's first row (row m0). For BT, Bm points at row n0.
// For !BT, Bm points at column n0 of B's first row.
// All dims assumed multiples of tile sizes (true for this problem).
// ---------------------------------------------------------------------------
template <bool BT>
__device__ __forceinline__ void gemm_mainloop(const float* __restrict__ A, int lda,
                                              const float* __restrict__ Bm, int ldb,
                                              int K, float acc[8][8])
{
    __shared__ float As[BK * BMP];
    __shared__ float Bs[BK * BMP];

    const int tid = threadIdx.x;      // 0..255
    const int tx  = tid & 15;
    const int ty  = tid >> 4;

    for (int k0 = 0; k0 < K; k0 += BK) {
        // Load A tile: BM x BK (2048 elems, 8 per thread), store transposed As[kk][m]
        #pragma unroll
        for (int i = 0; i < 8; i++) {
            int idx = tid + i * 256;
            int m  = idx >> 4;
            int kk = idx & 15;
            As[kk * BMP + m] = A[(size_t)m * lda + (k0 + kk)];
        }
        // Load B tile -> Bs[kk][n]
        #pragma unroll
        for (int i = 0; i < 8; i++) {
            int idx = tid + i * 256;
            if (BT) {
                int n  = idx >> 4;
                int kk = idx & 15;
                Bs[kk * BMP + n] = Bm[(size_t)n * ldb + (k0 + kk)];
            } else {
                int kk = idx >> 7;
                int n  = idx & 127;
                Bs[kk * BMP + n] = Bm[(size_t)(k0 + kk) * ldb + n];
            }
        }
        __syncthreads();

        #pragma unroll
        for (int kk = 0; kk < BK; kk++) {
            float a[8], b[8];
            #pragma unroll
            for (int i = 0; i < 4; i++) {
                float2 t = *(const float2*)(As + kk * BMP + ty * 8 + i * 2);
                a[2 * i] = t.x; a[2 * i + 1] = t.y;
            }
            #pragma unroll
            for (int j = 0; j < 4; j++) {
                float2 t = *(const float2*)(Bs + kk * BMP + tx * 8 + j * 2);
                b[2 * j] = t.x; b[2 * j + 1] = t.y;
            }
            #pragma unroll
            for (int i = 0; i < 8; i++)
                #pragma unroll
                for (int j = 0; j < 8; j++)
                    acc[i][j] = fmaf(a[i], b[j], acc[i][j]);
        }
        __syncthreads();
    }
}

// ---------------------------------------------------------------------------
// Stage 1: QKV projections. z=0:Q (scaled by 1/16), z=1:K, z=2:V
// X [B*T, E] @ W [E, HE] -> g_qkv[z] [B*T, HE]
// ---------------------------------------------------------------------------
__global__ __launch_bounds__(256) void qkv_kernel(const float* __restrict__ x,
                                                  const float* __restrict__ Wq,
                                                  const float* __restrict__ Wk,
                                                  const float* __restrict__ Wv)
{
    const int z = blockIdx.z;
    const float* W = (z == 0) ? Wq : (z == 1) ? Wk : Wv;
    const float scale = (z == 0) ? 0.0625f : 1.0f;   // 1/sqrt(E) = 1/16
    float* C = g_qkv + (size_t)z * B_ * T_ * HE_;

    const int m0 = blockIdx.y * BM;
    const int n0 = blockIdx.x * BN;

    float acc[8][8] = {};
    gemm_mainloop<false>(x + (size_t)m0 * E_, E_, W + n0, HE_, E_, acc);

    const int tx = threadIdx.x & 15, ty = threadIdx.x >> 4;
    #pragma unroll
    for (int i = 0; i < 8; i++) {
        size_t r = (size_t)(m0 + ty * 8 + i) * HE_;
        #pragma unroll
        for (int j = 0; j < 8; j++)
            C[r + n0 + tx * 8 + j] = acc[i][j] * scale;
    }
}

// ---------------------------------------------------------------------------
// Stage 2: scores S[b,h,q,k] = Qs[b,q,h,:] . K[b,k,h,:], masked -> -inf
// mask is int32 (0/1) per element, [B, T, T]
// ---------------------------------------------------------------------------
__global__ __launch_bounds__(256) void scores_kernel(const int* __restrict__ mask)
{
    const int z = blockIdx.z;          // b*H + h
    const int b = z >> 3;
    const int h = z & 7;

    const float* Q = g_qkv + (size_t)b * T_ * HE_ + h * E_;
    const float* K = g_qkv + (size_t)B_ * T_ * HE_ + (size_t)b * T_ * HE_ + h * E_;

    const int m0 = blockIdx.y * BM;    // query tile
    const int n0 = blockIdx.x * BN;    // key tile

    float acc[8][8] = {};
    gemm_mainloop<true>(Q + (size_t)m0 * HE_, HE_,
                        K + (size_t)n0 * HE_, HE_, E_, acc);

    float* S = g_s + (size_t)z * T_ * T_;
    const int* mrow = mask + (size_t)b * T_ * T_;

    const int tx = threadIdx.x & 15, ty = threadIdx.x >> 4;
    #pragma unroll
    for (int i = 0; i < 8; i++) {
        int q = m0 + ty * 8 + i;
        size_t r = (size_t)q * T_;
        #pragma unroll
        for (int j = 0; j < 8; j++) {
            int k = n0 + tx * 8 + j;
            S[r + k] = (mrow[r + k] != 0) ? NEG_INF : acc[i][j];
        }
    }
}

// ---------------------------------------------------------------------------
// Stage 3: row softmax over last dim (T=1024). Fully-masked rows -> 0.
// One block (256 threads) per row; 4 elements per thread.
// ---------------------------------------------------------------------------
__global__ __launch_bounds__(256) void softmax_kernel()
{
    float* p = g_s + (size_t)blockIdx.x * T_;
    const int t = threadIdx.x;

    float4 v = ((const float4*)p)[t];
    float mx = fmaxf(fmaxf(v.x, v.y), fmaxf(v.z, v.w));

    __shared__ float red[8];
    #pragma unroll
    for (int o = 16; o > 0; o >>= 1)
        mx = fmaxf(mx, __shfl_xor_sync(0xffffffff, mx, o));
    if ((t & 31) == 0) red[t >> 5] = mx;
    __syncthreads();
    float bm = red[0];
    #pragma unroll
    for (int i = 1; i < 8; i++) bm = fmaxf(bm, red[i]);
    __syncthreads();

    float4 e;
    float s;
    if (bm == NEG_INF) {
        e.x = e.y = e.z = e.w = 0.0f;
        s = 0.0f;
    } else {
        e.x = __expf(v.x - bm);
        e.y = __expf(v.y - bm);
        e.z = __expf(v.z - bm);
        e.w = __expf(v.w - bm);
        s = e.x + e.y + e.z + e.w;
    }
    #pragma unroll
    for (int o = 16; o > 0; o >>= 1)
        s += __shfl_xor_sync(0xffffffff, s, o);
    if ((t & 31) == 0) red[t >> 5] = s;
    __syncthreads();
    float tot = red[0];
    #pragma unroll
    for (int i = 1; i < 8; i++) tot += red[i];

    float inv = (tot > 0.0f) ? (1.0f / tot) : 0.0f;
    e.x *= inv; e.y *= inv; e.z *= inv; e.w *= inv;
    ((float4*)p)[t] = e;
}

// ---------------------------------------------------------------------------
// Stage 4: O[b,q,h,:] = sum_k P[b,h,q,k] * V[b,k,h,:]
// ---------------------------------------------------------------------------
__global__ __launch_bounds__(256) void attnv_kernel()
{
    const int z = blockIdx.z;
    const int b = z >> 3;
    const int h = z & 7;

    const float* S = g_s + (size_t)z * T_ * T_;
    const float* V = g_qkv + 2ULL * B_ * T_ * HE_ + (size_t)b * T_ * HE_ + h * E_;

    const int m0 = blockIdx.y * BM;    // query tile
    const int n0 = blockIdx.x * BN;    // head-dim tile (E=256 -> 2 tiles)

    float acc[8][8] = {};
    gemm_mainloop<false>(S + (size_t)m0 * T_, T_, V + n0, HE_, T_, acc);

    float* O = g_o + (size_t)b * T_ * HE_ + h * E_;
    const int tx = threadIdx.x & 15, ty = threadIdx.x >> 4;
    #pragma unroll
    for (int i = 0; i < 8; i++) {
        size_t r = (size_t)(m0 + ty * 8 + i) * HE_;
        #pragma unroll
        for (int j = 0; j < 8; j++)
            O[r + n0 + tx * 8 + j] = acc[i][j];
    }
}

// ---------------------------------------------------------------------------
// Stage 5: out = O [B*T, HE] @ Wfc [HE, E] + bfc
// ---------------------------------------------------------------------------
__global__ __launch_bounds__(256) void fc_kernel(const float* __restrict__ Wfc,
                                                 const float* __restrict__ bfc,
                                                 float* __restrict__ out)
{
    const int m0 = blockIdx.y * BM;
    const int n0 = blockIdx.x * BN;

    float acc[8][8] = {};
    gemm_mainloop<false>(g_o + (size_t)m0 * HE_, HE_, Wfc + n0, E_, HE_, acc);

    const int tx = threadIdx.x & 15, ty = threadIdx.x >> 4;
    #pragma unroll
    for (int j = 0; j < 8; j++) {
        float bias = bfc[n0 + tx * 8 + j];
        #pragma unroll
        for (int i = 0; i < 8; i++)
            out[(size_t)(m0 + ty * 8 + i) * E_ + n0 + tx * 8 + j] = acc[i][j] + bias;
    }
}

// ---------------------------------------------------------------------------
extern "C" void kernel_launch(void* const* d_in, const int* in_sizes, int n_in,
                              void* d_out, int out_size)
{
    const float* x   = (const float*)d_in[0];
    const float* Wq  = (const float*)d_in[1];
    const float* Wk  = (const float*)d_in[2];
    const float* Wv  = (const float*)d_in[3];
    const float* Wfc = (const float*)d_in[4];
    const float* bfc = (const float*)d_in[5];
    const int*   mask = (const int*)d_in[6];

    dim3 blk(256);

    // Stage 1: QKV projections (z selects Q/K/V)
    qkv_kernel<<<dim3(HE_ / BN, (B_ * T_) / BM, 3), blk>>>(x, Wq, Wk, Wv);

    // Stage 2: masked scores
    scores_kernel<<<dim3(T_ / BN, T_ / BM, B_ * H_), blk>>>(mask);

    // Stage 3: softmax (one block per row)
    softmax_kernel<<<B_ * H_ * T_, 256>>>();

    // Stage 4: attn @ V
    attnv_kernel<<<dim3(E_ / BN, T_ / BM, B_ * H_), blk>>>();

    // Stage 5: FC + bias
    fc_kernel<<<dim3(E_ / BN, (B_ * T_) / BM, 1), blk>>>(Wfc, bfc, (float*)d_out);
}

// round 3
// speedup vs baseline: 2.9278x; 2.9278x over previous
#include <cuda_runtime.h>

// Problem constants
#define B_   8
#define T_   1024
#define E_   256
#define H_   8
#define HE_  2048   // H_*E_

// Tile config: 128x128 CTA tile, BK=16, 256 threads (8 warps, 2x4), 64x32 warp tile
#define BM   128
#define BN   128
#define BK   16
#define BMP  132    // padded smem row stride (floats), 16B-aligned rows

#define NEG_INF __int_as_float(0xff800000)

// Scratch (static device arrays: allocation-guard-safe)
__device__ float g_qkv[3ULL * B_ * T_ * HE_];             // Q, K, V each [B, T, HE]
__device__ float g_s[(size_t)B_ * H_ * T_ * T_];          // scores/probs [B*H, T, T]
__device__ float g_o[(size_t)B_ * T_ * HE_];              // attn@V [B, T, HE]

__device__ __forceinline__ unsigned f2tf32(float f) {
    unsigned u;
    asm("cvt.rna.tf32.f32 %0, %1;" : "=r"(u) : "f"(f));
    return u;
}

__device__ __forceinline__ void mma_tf32(float c[4], const unsigned a[4], const unsigned b[2]) {
    asm("mma.sync.aligned.m16n8k8.row.col.f32.tf32.tf32.f32 "
        "{%0,%1,%2,%3}, {%4,%5,%6,%7}, {%8,%9}, {%0,%1,%2,%3};"
        : "+f"(c[0]), "+f"(c[1]), "+f"(c[2]), "+f"(c[3])
        : "r"(a[0]), "r"(a[1]), "r"(a[2]), "r"(a[3]), "r"(b[0]), "r"(b[1]));
}

// ---------------------------------------------------------------------------
// Tensor-core GEMM mainloop: BMxBN tile of A(MxK) * op(B)(KxN) in tf32.
// BT=false: B is [K, N] row-major (ldb = row stride)
// BT=true : B is [N, K] row-major (ldb = row stride)  -> C = A * B^T
// A points at tile's first row. For BT, Bm points at row n0; else at col n0.
// acc[mi][ni][4]: per-warp 64x32 accumulator fragments.
// ---------------------------------------------------------------------------
template <bool BT>
__device__ __forceinline__ void gemm_tc(const float* __restrict__ A, int lda,
                                        const float* __restrict__ Bm, int ldb,
                                        int K, float acc[4][4][4])
{
    __shared__ float As[BK][BMP];   // tf32 bit patterns, [k][m]
    __shared__ float Bs[BK][BMP];   // tf32 bit patterns, [k][n]

    const int tid  = threadIdx.x;
    const int lane = tid & 31;
    const int warp = tid >> 5;
    const int wm   = warp >> 2;          // 0..1
    const int wn   = warp & 3;           // 0..3
    const int g    = lane >> 2;          // group 0..7
    const int q    = lane & 3;           // quad 0..3

    for (int k0 = 0; k0 < K; k0 += BK) {
        // ---- stage A tile: 128x16 = 512 float4 quads, 2 per thread ----
        #pragma unroll
        for (int i = 0; i < 2; i++) {
            int qd = tid + i * 256;
            int m  = qd >> 2;
            int kq = (qd & 3) * 4;
            float4 v = *(const float4*)(A + (size_t)m * lda + k0 + kq);
            As[kq + 0][m] = __uint_as_float(f2tf32(v.x));
            As[kq + 1][m] = __uint_as_float(f2tf32(v.y));
            As[kq + 2][m] = __uint_as_float(f2tf32(v.z));
            As[kq + 3][m] = __uint_as_float(f2tf32(v.w));
        }
        // ---- stage B tile ----
        #pragma unroll
        for (int i = 0; i < 2; i++) {
            int qd = tid + i * 256;
            if (BT) {
                int n  = qd >> 2;
                int kq = (qd & 3) * 4;
                float4 v = *(const float4*)(Bm + (size_t)n * ldb + k0 + kq);
                Bs[kq + 0][n] = __uint_as_float(f2tf32(v.x));
                Bs[kq + 1][n] = __uint_as_float(f2tf32(v.y));
                Bs[kq + 2][n] = __uint_as_float(f2tf32(v.z));
                Bs[kq + 3][n] = __uint_as_float(f2tf32(v.w));
            } else {
                int kk = qd >> 5;
                int nq = (qd & 31) * 4;
                float4 v = *(const float4*)(Bm + (size_t)(k0 + kk) * ldb + nq);
                uint4 u;
                u.x = f2tf32(v.x); u.y = f2tf32(v.y);
                u.z = f2tf32(v.z); u.w = f2tf32(v.w);
                *(uint4*)&Bs[kk][nq] = u;
            }
        }
        __syncthreads();

        // ---- compute: two k-steps of 8 ----
        #pragma unroll
        for (int ks = 0; ks < 2; ks++) {
            const int kb = ks * 8;
            unsigned a[4][4], b[4][2];
            #pragma unroll
            for (int mi = 0; mi < 4; mi++) {
                int m = wm * 64 + mi * 16;
                a[mi][0] = __float_as_uint(As[kb + q    ][m + g    ]);
                a[mi][1] = __float_as_uint(As[kb + q    ][m + g + 8]);
                a[mi][2] = __float_as_uint(As[kb + q + 4][m + g    ]);
                a[mi][3] = __float_as_uint(As[kb + q + 4][m + g + 8]);
            }
            #pragma unroll
            for (int ni = 0; ni < 4; ni++) {
                int n = wn * 32 + ni * 8;
                b[ni][0] = __float_as_uint(Bs[kb + q    ][n + g]);
                b[ni][1] = __float_as_uint(Bs[kb + q + 4][n + g]);
            }
            #pragma unroll
            for (int mi = 0; mi < 4; mi++)
                #pragma unroll
                for (int ni = 0; ni < 4; ni++)
                    mma_tf32(acc[mi][ni], a[mi], b[ni]);
        }
        __syncthreads();
    }
}

// Epilogue index helpers: element (mi,ni,r) lives at
// row = wm*64 + mi*16 + g + (r>=2 ? 8 : 0), col = wn*32 + ni*8 + 2q + (r&1)
struct Frag {
    int wm, wn, g, q;
    __device__ __forceinline__ Frag() {
        int tid = threadIdx.x, lane = tid & 31, warp = tid >> 5;
        wm = warp >> 2; wn = warp & 3; g = lane >> 2; q = lane & 3;
    }
    __device__ __forceinline__ int row(int mi, int hi) const { return wm * 64 + mi * 16 + g + hi * 8; }
    __device__ __forceinline__ int col(int ni) const { return wn * 32 + ni * 8 + 2 * q; }
};

// ---------------------------------------------------------------------------
// Stage 1: QKV projections. z=0:Q (scaled 1/16), z=1:K, z=2:V
// ---------------------------------------------------------------------------
__global__ __launch_bounds__(256) void qkv_kernel(const float* __restrict__ x,
                                                  const float* __restrict__ Wq,
                                                  const float* __restrict__ Wk,
                                                  const float* __restrict__ Wv)
{
    const int z = blockIdx.z;
    const float* W = (z == 0) ? Wq : (z == 1) ? Wk : Wv;
    const float scale = (z == 0) ? 0.0625f : 1.0f;
    float* C = g_qkv + (size_t)z * B_ * T_ * HE_;

    const int m0 = blockIdx.y * BM;
    const int n0 = blockIdx.x * BN;

    float acc[4][4][4] = {};
    gemm_tc<false>(x + (size_t)m0 * E_, E_, W + n0, HE_, E_, acc);

    Frag f;
    #pragma unroll
    for (int mi = 0; mi < 4; mi++)
        #pragma unroll
        for (int ni = 0; ni < 4; ni++) {
            int c = n0 + f.col(ni);
            float2 lo = { acc[mi][ni][0] * scale, acc[mi][ni][1] * scale };
            float2 hi = { acc[mi][ni][2] * scale, acc[mi][ni][3] * scale };
            *(float2*)&C[(size_t)(m0 + f.row(mi, 0)) * HE_ + c] = lo;
            *(float2*)&C[(size_t)(m0 + f.row(mi, 1)) * HE_ + c] = hi;
        }
}

// ---------------------------------------------------------------------------
// Stage 2: scores S = Q.K^T with mask -> -inf. mask int32 [B,T,T]
// ---------------------------------------------------------------------------
__global__ __launch_bounds__(256) void scores_kernel(const int* __restrict__ mask)
{
    const int z = blockIdx.z;   // b*H + h
    const int b = z >> 3;
    const int h = z & 7;

    const float* Q = g_qkv + (size_t)b * T_ * HE_ + h * E_;
    const float* K = g_qkv + (size_t)B_ * T_ * HE_ + (size_t)b * T_ * HE_ + h * E_;

    const int m0 = blockIdx.y * BM;
    const int n0 = blockIdx.x * BN;

    float acc[4][4][4] = {};
    gemm_tc<true>(Q + (size_t)m0 * HE_, HE_, K + (size_t)n0 * HE_, HE_, E_, acc);

    float* S = g_s + (size_t)z * T_ * T_;
    const int* mrow = mask + (size_t)b * T_ * T_;

    Frag f;
    #pragma unroll
    for (int mi = 0; mi < 4; mi++)
        #pragma unroll
        for (int ni = 0; ni < 4; ni++) {
            int c = n0 + f.col(ni);
            #pragma unroll
            for (int hi = 0; hi < 2; hi++) {
                size_t r = (size_t)(m0 + f.row(mi, hi)) * T_;
                float v0 = (mrow[r + c    ] != 0) ? NEG_INF : acc[mi][ni][hi * 2    ];
                float v1 = (mrow[r + c + 1] != 0) ? NEG_INF : acc[mi][ni][hi * 2 + 1];
                *(float2*)&S[r + c] = make_float2(v0, v1);
            }
        }
}

// ---------------------------------------------------------------------------
// Stage 3: row softmax over T=1024; fully-masked rows -> 0.
// ---------------------------------------------------------------------------
__global__ __launch_bounds__(256) void softmax_kernel()
{
    float* p = g_s + (size_t)blockIdx.x * T_;
    const int t = threadIdx.x;

    float4 v = ((const float4*)p)[t];
    float mx = fmaxf(fmaxf(v.x, v.y), fmaxf(v.z, v.w));

    __shared__ float red[8];
    #pragma unroll
    for (int o = 16; o > 0; o >>= 1)
        mx = fmaxf(mx, __shfl_xor_sync(0xffffffff, mx, o));
    if ((t & 31) == 0) red[t >> 5] = mx;
    __syncthreads();
    float bm = red[0];
    #pragma unroll
    for (int i = 1; i < 8; i++) bm = fmaxf(bm, red[i]);
    __syncthreads();

    float4 e;
    float s;
    if (bm == NEG_INF) {
        e.x = e.y = e.z = e.w = 0.0f;
        s = 0.0f;
    } else {
        e.x = __expf(v.x - bm);
        e.y = __expf(v.y - bm);
        e.z = __expf(v.z - bm);
        e.w = __expf(v.w - bm);
        s = e.x + e.y + e.z + e.w;
    }
    #pragma unroll
    for (int o = 16; o > 0; o >>= 1)
        s += __shfl_xor_sync(0xffffffff, s, o);
    if ((t & 31) == 0) red[t >> 5] = s;
    __syncthreads();
    float tot = red[0];
    #pragma unroll
    for (int i = 1; i < 8; i++) tot += red[i];

    float inv = (tot > 0.0f) ? (1.0f / tot) : 0.0f;
    e.x *= inv; e.y *= inv; e.z *= inv; e.w *= inv;
    ((float4*)p)[t] = e;
}

// ---------------------------------------------------------------------------
// Stage 4: O[b,q,h,:] = sum_k P[b,h,q,k] * V[b,k,h,:]
// ---------------------------------------------------------------------------
__global__ __launch_bounds__(256) void attnv_kernel()
{
    const int z = blockIdx.z;
    const int b = z >> 3;
    const int h = z & 7;

    const float* S = g_s + (size_t)z * T_ * T_;
    const float* V = g_qkv + 2ULL * B_ * T_ * HE_ + (size_t)b * T_ * HE_ + h * E_;

    const int m0 = blockIdx.y * BM;
    const int n0 = blockIdx.x * BN;

    float acc[4][4][4] = {};
    gemm_tc<false>(S + (size_t)m0 * T_, T_, V + n0, HE_, T_, acc);

    float* O = g_o + (size_t)b * T_ * HE_ + h * E_;
    Frag f;
    #pragma unroll
    for (int mi = 0; mi < 4; mi++)
        #pragma unroll
        for (int ni = 0; ni < 4; ni++) {
            int c = n0 + f.col(ni);
            *(float2*)&O[(size_t)(m0 + f.row(mi, 0)) * HE_ + c] = make_float2(acc[mi][ni][0], acc[mi][ni][1]);
            *(float2*)&O[(size_t)(m0 + f.row(mi, 1)) * HE_ + c] = make_float2(acc[mi][ni][2], acc[mi][ni][3]);
        }
}

// ---------------------------------------------------------------------------
// Stage 5: out = O [B*T, HE] @ Wfc [HE, E] + bfc
// ---------------------------------------------------------------------------
__global__ __launch_bounds__(256) void fc_kernel(const float* __restrict__ Wfc,
                                                 const float* __restrict__ bfc,
                                                 float* __restrict__ out)
{
    const int m0 = blockIdx.y * BM;
    const int n0 = blockIdx.x * BN;

    float acc[4][4][4] = {};
    gemm_tc<false>(g_o + (size_t)m0 * HE_, HE_, Wfc + n0, E_, HE_, acc);

    Frag f;
    #pragma unroll
    for (int mi = 0; mi < 4; mi++)
        #pragma unroll
        for (int ni = 0; ni < 4; ni++) {
            int c = n0 + f.col(ni);
            float b0 = bfc[c], b1 = bfc[c + 1];
            *(float2*)&out[(size_t)(m0 + f.row(mi, 0)) * E_ + c] =
                make_float2(acc[mi][ni][0] + b0, acc[mi][ni][1] + b1);
            *(float2*)&out[(size_t)(m0 + f.row(mi, 1)) * E_ + c] =
                make_float2(acc[mi][ni][2] + b0, acc[mi][ni][3] + b1);
        }
}

// ---------------------------------------------------------------------------
extern "C" void kernel_launch(void* const* d_in, const int* in_sizes, int n_in,
                              void* d_out, int out_size)
{
    const float* x   = (const float*)d_in[0];
    const float* Wq  = (const float*)d_in[1];
    const float* Wk  = (const float*)d_in[2];
    const float* Wv  = (const float*)d_in[3];
    const float* Wfc = (const float*)d_in[4];
    const float* bfc = (const float*)d_in[5];
    const int*   mask = (const int*)d_in[6];

    dim3 blk(256);

    qkv_kernel<<<dim3(HE_ / BN, (B_ * T_) / BM, 3), blk>>>(x, Wq, Wk, Wv);
    scores_kernel<<<dim3(T_ / BN, T_ / BM, B_ * H_), blk>>>(mask);
    softmax_kernel<<<B_ * H_ * T_, 256>>>();
    attnv_kernel<<<dim3(E_ / BN, T_ / BM, B_ * H_), blk>>>();
    fc_kernel<<<dim3(E_ / BN, (B_ * T_) / BM, 1), blk>>>(Wfc, bfc, (float*)d_out);
}

// round 4
// speedup vs baseline: 4.2022x; 1.4353x over previous
#include <cuda_runtime.h>

// Problem constants
#define B_   8
#define T_   1024
#define E_   256
#define H_   8
#define HE_  2048   // H_*E_

// Tile config: 128x128 CTA tile, BK=16, 256 threads (8 warps, 2x4), 64x32 warp tile
#define BM   128
#define BN   128
#define BK   16
#define BKP  20     // [m][k] smem row stride (words): 20g mod 32 covers all banks
#define BNP  136    // [k][n] smem row stride (words): 8q+g covers all banks

#define NEG_INF __int_as_float(0xff800000)

// Scratch (static device arrays: allocation-guard-safe)
__device__ float g_qkv[3ULL * B_ * T_ * HE_];             // Q, K, V each [B, T, HE] (tf32-rounded)
__device__ float g_s[(size_t)B_ * H_ * T_ * T_];          // scores -> probs [B*H, T, T]
__device__ float g_o[(size_t)B_ * T_ * HE_];              // attn@V [B, T, HE] (tf32-rounded)
// tf32-rounded copies of raw inputs
__device__ float g_xr[(size_t)B_ * T_ * E_];              // x
__device__ float g_wr[4ULL * E_ * HE_];                   // Wq, Wk, Wv, Wfc (Wfc is [HE,E], same elem count)

__device__ __forceinline__ unsigned f2tf32(float f) {
    unsigned u;
    asm("cvt.rna.tf32.f32 %0, %1;" : "=r"(u) : "f"(f));
    return u;
}
__device__ __forceinline__ float rtf(float f) { return __uint_as_float(f2tf32(f)); }

__device__ __forceinline__ void mma_tf32(float c[4], const unsigned a[4], const unsigned b[2]) {
    asm("mma.sync.aligned.m16n8k8.row.col.f32.tf32.tf32.f32 "
        "{%0,%1,%2,%3}, {%4,%5,%6,%7}, {%8,%9}, {%0,%1,%2,%3};"
        : "+f"(c[0]), "+f"(c[1]), "+f"(c[2]), "+f"(c[3])
        : "r"(a[0]), "r"(a[1]), "r"(a[2]), "r"(a[3]), "r"(b[0]), "r"(b[1]));
}

__device__ __forceinline__ void cp16(void* smem_dst, const void* gmem_src) {
    unsigned d = (unsigned)__cvta_generic_to_shared(smem_dst);
    asm volatile("cp.async.cg.shared.global [%0], [%1], 16;" :: "r"(d), "l"(gmem_src));
}

// ---------------------------------------------------------------------------
// Tensor-core GEMM mainloop (double-buffered cp.async, tf32 inputs pre-rounded).
// BT=false: B is [K, N] row-major  -> Bs stored [k][BNP]
// BT=true : B is [N, K] row-major  -> C = A * B^T, Bs stored [n][BKP]
// A always [M, K] row-major -> As stored [m][BKP].
// acc[mi][ni][4]: per-warp 64x32 accumulator fragments.
// ---------------------------------------------------------------------------
template <bool BT>
__device__ __forceinline__ void gemm_tc(const float* __restrict__ A, int lda,
                                        const float* __restrict__ Bm, int ldb,
                                        int K, float acc[4][4][4])
{
    __shared__ float As[2][BM * BKP];
    __shared__ float Bs[2][BM * BKP];   // 2560 words covers both layouts (16*136=2176)

    const int tid  = threadIdx.x;
    const int lane = tid & 31;
    const int warp = tid >> 5;
    const int wm   = warp >> 2;          // 0..1
    const int wn   = warp & 3;           // 0..3
    const int g    = lane >> 2;          // 0..7
    const int q    = lane & 3;           // 0..3

    auto stage = [&](int buf, int k0) {
        #pragma unroll
        for (int i = 0; i < 2; i++) {
            int c  = tid + i * 256;
            int m  = c >> 2;
            int ko = (c & 3) * 4;
            cp16(&As[buf][m * BKP + ko], A + (size_t)m * lda + k0 + ko);
        }
        #pragma unroll
        for (int i = 0; i < 2; i++) {
            int c = tid + i * 256;
            if (BT) {
                int n  = c >> 2;
                int ko = (c & 3) * 4;
                cp16(&Bs[buf][n * BKP + ko], Bm + (size_t)n * ldb + k0 + ko);
            } else {
                int kk = c >> 5;
                int no = (c & 31) * 4;
                cp16(&Bs[buf][kk * BNP + no], Bm + (size_t)(k0 + kk) * ldb + no);
            }
        }
        asm volatile("cp.async.commit_group;");
    };

    stage(0, 0);

    const int niter = K / BK;
    for (int it = 0; it < niter; it++) {
        const int buf = it & 1;
        if (it + 1 < niter) {
            stage(buf ^ 1, (it + 1) * BK);
            asm volatile("cp.async.wait_group 1;");
        } else {
            asm volatile("cp.async.wait_group 0;");
        }
        __syncthreads();

        #pragma unroll
        for (int ks = 0; ks < 2; ks++) {
            const int kb = ks * 8;
            unsigned a[4][4], b[4][2];
            #pragma unroll
            for (int mi = 0; mi < 4; mi++) {
                int m = wm * 64 + mi * 16;
                a[mi][0] = __float_as_uint(As[buf][(m + g    ) * BKP + kb + q    ]);
                a[mi][1] = __float_as_uint(As[buf][(m + g + 8) * BKP + kb + q    ]);
                a[mi][2] = __float_as_uint(As[buf][(m + g    ) * BKP + kb + q + 4]);
                a[mi][3] = __float_as_uint(As[buf][(m + g + 8) * BKP + kb + q + 4]);
            }
            #pragma unroll
            for (int ni = 0; ni < 4; ni++) {
                int n = wn * 32 + ni * 8;
                if (BT) {
                    b[ni][0] = __float_as_uint(Bs[buf][(n + g) * BKP + kb + q    ]);
                    b[ni][1] = __float_as_uint(Bs[buf][(n + g) * BKP + kb + q + 4]);
                } else {
                    b[ni][0] = __float_as_uint(Bs[buf][(kb + q    ) * BNP + n + g]);
                    b[ni][1] = __float_as_uint(Bs[buf][(kb + q + 4) * BNP + n + g]);
                }
            }
            #pragma unroll
            for (int mi = 0; mi < 4; mi++)
                #pragma unroll
                for (int ni = 0; ni < 4; ni++)
                    mma_tf32(acc[mi][ni], a[mi], b[ni]);
        }
        __syncthreads();
    }
}

// Epilogue index helper: element (mi,ni,r): row = wm*64+mi*16+g+(r>=2?8:0), col = wn*32+ni*8+2q+(r&1)
struct Frag {
    int wm, wn, g, q;
    __device__ __forceinline__ Frag() {
        int tid = threadIdx.x, lane = tid & 31, warp = tid >> 5;
        wm = warp >> 2; wn = warp & 3; g = lane >> 2; q = lane & 3;
    }
    __device__ __forceinline__ int row(int mi, int hi) const { return wm * 64 + mi * 16 + g + hi * 8; }
    __device__ __forceinline__ int col(int ni) const { return wn * 32 + ni * 8 + 2 * q; }
};

// ---------------------------------------------------------------------------
// Stage 0: pre-round raw inputs to tf32 (x, Wq, Wk, Wv, Wfc), float4-wide.
// ---------------------------------------------------------------------------
#define XR_N   ((size_t)B_ * T_ * E_)          // 2M floats
#define W_N    ((size_t)E_ * HE_)              // 512K floats each
__global__ __launch_bounds__(256) void round_kernel(const float* __restrict__ x,
                                                    const float* __restrict__ Wq,
                                                    const float* __restrict__ Wk,
                                                    const float* __restrict__ Wv,
                                                    const float* __restrict__ Wfc)
{
    size_t i = ((size_t)blockIdx.x * 256 + threadIdx.x) * 4;
    const float* src;
    float* dst;
    size_t off;
    if (i < XR_N)                 { src = x;   dst = g_xr;            off = i; }
    else if (i < XR_N + W_N)      { src = Wq;  dst = g_wr;            off = i - XR_N; }
    else if (i < XR_N + 2 * W_N)  { src = Wk;  dst = g_wr + W_N;      off = i - XR_N - W_N; }
    else if (i < XR_N + 3 * W_N)  { src = Wv;  dst = g_wr + 2 * W_N;  off = i - XR_N - 2 * W_N; }
    else                          { src = Wfc; dst = g_wr + 3 * W_N;  off = i - XR_N - 3 * W_N; }
    float4 v = *(const float4*)(src + off);
    v.x = rtf(v.x); v.y = rtf(v.y); v.z = rtf(v.z); v.w = rtf(v.w);
    *(float4*)(dst + off) = v;
}

// ---------------------------------------------------------------------------
// Stage 1: QKV projections. z=0:Q (scaled 1/16), z=1:K, z=2:V. Outputs tf32-rounded.
// ---------------------------------------------------------------------------
__global__ __launch_bounds__(256) void qkv_kernel()
{
    const int z = blockIdx.z;
    const float* W = g_wr + (size_t)z * W_N;
    const float scale = (z == 0) ? 0.0625f : 1.0f;
    float* C = g_qkv + (size_t)z * B_ * T_ * HE_;

    const int m0 = blockIdx.y * BM;
    const int n0 = blockIdx.x * BN;

    float acc[4][4][4] = {};
    gemm_tc<false>(g_xr + (size_t)m0 * E_, E_, W + n0, HE_, E_, acc);

    Frag f;
    #pragma unroll
    for (int mi = 0; mi < 4; mi++)
        #pragma unroll
        for (int ni = 0; ni < 4; ni++) {
            int c = n0 + f.col(ni);
            *(float2*)&C[(size_t)(m0 + f.row(mi, 0)) * HE_ + c] =
                make_float2(rtf(acc[mi][ni][0] * scale), rtf(acc[mi][ni][1] * scale));
            *(float2*)&C[(size_t)(m0 + f.row(mi, 1)) * HE_ + c] =
                make_float2(rtf(acc[mi][ni][2] * scale), rtf(acc[mi][ni][3] * scale));
        }
}

// ---------------------------------------------------------------------------
// Stage 2: scores S = Q.K^T with mask -> -inf. mask int32 [B,T,T]
// ---------------------------------------------------------------------------
__global__ __launch_bounds__(256) void scores_kernel(const int* __restrict__ mask)
{
    const int z = blockIdx.z;   // b*H + h
    const int b = z >> 3;
    const int h = z & 7;

    const float* Q = g_qkv + (size_t)b * T_ * HE_ + h * E_;
    const float* K = g_qkv + (size_t)B_ * T_ * HE_ + (size_t)b * T_ * HE_ + h * E_;

    const int m0 = blockIdx.y * BM;
    const int n0 = blockIdx.x * BN;

    float acc[4][4][4] = {};
    gemm_tc<true>(Q + (size_t)m0 * HE_, HE_, K + (size_t)n0 * HE_, HE_, E_, acc);

    float* S = g_s + (size_t)z * T_ * T_;
    const int* mrow = mask + (size_t)b * T_ * T_;

    Frag f;
    #pragma unroll
    for (int mi = 0; mi < 4; mi++)
        #pragma unroll
        for (int ni = 0; ni < 4; ni++) {
            int c = n0 + f.col(ni);
            #pragma unroll
            for (int hi = 0; hi < 2; hi++) {
                size_t r = (size_t)(m0 + f.row(mi, hi)) * T_;
                float v0 = (mrow[r + c    ] != 0) ? NEG_INF : acc[mi][ni][hi * 2    ];
                float v1 = (mrow[r + c + 1] != 0) ? NEG_INF : acc[mi][ni][hi * 2 + 1];
                *(float2*)&S[r + c] = make_float2(v0, v1);
            }
        }
}

// ---------------------------------------------------------------------------
// Stage 3: row softmax over T=1024; fully-masked rows -> 0. Output tf32-rounded.
// ---------------------------------------------------------------------------
__global__ __launch_bounds__(256) void softmax_kernel()
{
    float* p = g_s + (size_t)blockIdx.x * T_;
    const int t = threadIdx.x;

    float4 v = ((const float4*)p)[t];
    float mx = fmaxf(fmaxf(v.x, v.y), fmaxf(v.z, v.w));

    __shared__ float red[8];
    #pragma unroll
    for (int o = 16; o > 0; o >>= 1)
        mx = fmaxf(mx, __shfl_xor_sync(0xffffffff, mx, o));
    if ((t & 31) == 0) red[t >> 5] = mx;
    __syncthreads();
    float bm = red[0];
    #pragma unroll
    for (int i = 1; i < 8; i++) bm = fmaxf(bm, red[i]);
    __syncthreads();

    float4 e;
    float s;
    if (bm == NEG_INF) {
        e.x = e.y = e.z = e.w = 0.0f;
        s = 0.0f;
    } else {
        e.x = __expf(v.x - bm);
        e.y = __expf(v.y - bm);
        e.z = __expf(v.z - bm);
        e.w = __expf(v.w - bm);
        s = e.x + e.y + e.z + e.w;
    }
    #pragma unroll
    for (int o = 16; o > 0; o >>= 1)
        s += __shfl_xor_sync(0xffffffff, s, o);
    if ((t & 31) == 0) red[t >> 5] = s;
    __syncthreads();
    float tot = red[0];
    #pragma unroll
    for (int i = 1; i < 8; i++) tot += red[i];

    float inv = (tot > 0.0f) ? (1.0f / tot) : 0.0f;
    e.x = rtf(e.x * inv); e.y = rtf(e.y * inv);
    e.z = rtf(e.z * inv); e.w = rtf(e.w * inv);
    ((float4*)p)[t] = e;
}

// ---------------------------------------------------------------------------
// Stage 4: O[b,q,h,:] = sum_k P[b,h,q,k] * V[b,k,h,:]. Output tf32-rounded.
// ---------------------------------------------------------------------------
__global__ __launch_bounds__(256) void attnv_kernel()
{
    const int z = blockIdx.z;
    const int b = z >> 3;
    const int h = z & 7;

    const float* S = g_s + (size_t)z * T_ * T_;
    const float* V = g_qkv + 2ULL * B_ * T_ * HE_ + (size_t)b * T_ * HE_ + h * E_;

    const int m0 = blockIdx.y * BM;
    const int n0 = blockIdx.x * BN;

    float acc[4][4][4] = {};
    gemm_tc<false>(S + (size_t)m0 * T_, T_, V + n0, HE_, T_, acc);

    float* O = g_o + (size_t)b * T_ * HE_ + h * E_;
    Frag f;
    #pragma unroll
    for (int mi = 0; mi < 4; mi++)
        #pragma unroll
        for (int ni = 0; ni < 4; ni++) {
            int c = n0 + f.col(ni);
            *(float2*)&O[(size_t)(m0 + f.row(mi, 0)) * HE_ + c] =
                make_float2(rtf(acc[mi][ni][0]), rtf(acc[mi][ni][1]));
            *(float2*)&O[(size_t)(m0 + f.row(mi, 1)) * HE_ + c] =
                make_float2(rtf(acc[mi][ni][2]), rtf(acc[mi][ni][3]));
        }
}

// ---------------------------------------------------------------------------
// Stage 5: out = O [B*T, HE] @ Wfc [HE, E] + bfc
// ---------------------------------------------------------------------------
__global__ __launch_bounds__(256) void fc_kernel(const float* __restrict__ bfc,
                                                 float* __restrict__ out)
{
    const int m0 = blockIdx.y * BM;
    const int n0 = blockIdx.x * BN;

    float acc[4][4][4] = {};
    gemm_tc<false>(g_o + (size_t)m0 * HE_, HE_, g_wr + 3 * W_N + n0, E_, HE_, acc);

    Frag f;
    #pragma unroll
    for (int mi = 0; mi < 4; mi++)
        #pragma unroll
        for (int ni = 0; ni < 4; ni++) {
            int c = n0 + f.col(ni);
            float b0 = bfc[c], b1 = bfc[c + 1];
            *(float2*)&out[(size_t)(m0 + f.row(mi, 0)) * E_ + c] =
                make_float2(acc[mi][ni][0] + b0, acc[mi][ni][1] + b1);
            *(float2*)&out[(size_t)(m0 + f.row(mi, 1)) * E_ + c] =
                make_float2(acc[mi][ni][2] + b0, acc[mi][ni][3] + b1);
        }
}

// ---------------------------------------------------------------------------
extern "C" void kernel_launch(void* const* d_in, const int* in_sizes, int n_in,
                              void* d_out, int out_size)
{
    const float* x   = (const float*)d_in[0];
    const float* Wq  = (const float*)d_in[1];
    const float* Wk  = (const float*)d_in[2];
    const float* Wv  = (const float*)d_in[3];
    const float* Wfc = (const float*)d_in[4];
    const float* bfc = (const float*)d_in[5];
    const int*   mask = (const int*)d_in[6];

    dim3 blk(256);

    size_t total4 = (XR_N + 4 * W_N) / 4;           // float4 count
    round_kernel<<<(unsigned)(total4 / 256), blk>>>(x, Wq, Wk, Wv, Wfc);

    qkv_kernel<<<dim3(HE_ / BN, (B_ * T_) / BM, 3), blk>>>();
    scores_kernel<<<dim3(T_ / BN, T_ / BM, B_ * H_), blk>>>(mask);
    softmax_kernel<<<B_ * H_ * T_, 256>>>();
    attnv_kernel<<<dim3(E_ / BN, T_ / BM, B_ * H_), blk>>>();
    fc_kernel<<<dim3(E_ / BN, (B_ * T_) / BM, 1), blk>>>(bfc, (float*)d_out);
}